// round 6
// baseline (speedup 1.0000x reference)
#include <cuda_runtime.h>

#define BB 64
#define SS 1024
#define DD 16
#define NSPLIT 4
#define TOK (BB * SS)

// Scratch (allocation-free rule: __device__ globals)
__device__ float4 g_part[NSPLIT * TOK]; // per-split partial (l, a0, a1, 0)
__device__ float  g_A[256];             // diag(g) @ (W1W2W3 + I)
__device__ float  g_csA[16];            // column sums of g_A
__device__ float  g_bA[16];             // b @ (W1W2W3+I) + bc
__device__ float  g_O[256];             // diag(g) @ Wo
__device__ float  g_csO[16];            // column sums of g_O
__device__ float  g_bO[16];             // b @ Wo + bo

__device__ __forceinline__ float ex2_approx(float x) {
    float y;
    asm("ex2.approx.f32 %0, %1;" : "=f"(y) : "f"(x));
    return y;
}

// ---------------------------------------------------------------------------
// Kernel A: fused QKV + attention (4-way KV block split) + weight precompute.
// Grid (5, NSPLIT, BB), 256 threads.
//   blockIdx.x in [0,4): attention s-chunk; x==4 && y==0 && z==0: precompute.
// Each attention block computes its KV quarter and its Q values from x
// directly (no qkv kernel, no g_q/g_kv globals).
// ---------------------------------------------------------------------------
__global__ void __launch_bounds__(256)
attn_kernel(const float* __restrict__ x,
            const float* __restrict__ Wq, const float* __restrict__ bq,
            const float* __restrict__ Wk, const float* __restrict__ bk,
            const float* __restrict__ Wv, const float* __restrict__ bv,
            const float* __restrict__ W1, const float* __restrict__ b1,
            const float* __restrict__ W2, const float* __restrict__ b2,
            const float* __restrict__ W3, const float* __restrict__ b3,
            const float* __restrict__ ln_g, const float* __restrict__ ln_b,
            const float* __restrict__ Wo, const float* __restrict__ bo)
{
    int tid = threadIdx.x;

    if (blockIdx.x == 4) {
        // ------- precompute folded epilogue weights (one block) -------
        if (blockIdx.y != 0 || blockIdx.z != 0) return;
        __shared__ float s1[256], s2[256], s3[256], s12[256];
        __shared__ float sA[256], sAraw[256], sO[256];
        __shared__ float sbp[16], sbc[16], sg[16], sb[16];
        int r = tid >> 4, c = tid & 15;
        s1[tid] = W1[tid]; s2[tid] = W2[tid]; s3[tid] = W3[tid];
        if (tid < 16) { sg[tid] = ln_g[tid]; sb[tid] = ln_b[tid]; }
        __syncthreads();

        float acc = 0.f;
        #pragma unroll
        for (int k = 0; k < 16; k++) acc = fmaf(s1[r*16+k], s2[k*16+c], acc);
        s12[tid] = acc;
        if (tid < 16) {                 // b1@W2 + b2
            float t = b2[tid];
            #pragma unroll
            for (int k = 0; k < 16; k++) t = fmaf(b1[k], s2[k*16+tid], t);
            sbp[tid] = t;
        }
        __syncthreads();

        float w123 = 0.f;
        #pragma unroll
        for (int k = 0; k < 16; k++) w123 = fmaf(s12[r*16+k], s3[k*16+c], w123);
        float A = w123 + (r == c ? 1.0f : 0.0f);   // residual folded in
        sAraw[tid] = A;
        sA[tid] = sg[r] * A;
        sO[tid] = sg[r] * Wo[tid];
        if (tid < 16) {                 // bc = (b1@W2+b2)@W3 + b3
            float t = b3[tid];
            #pragma unroll
            for (int k = 0; k < 16; k++) t = fmaf(sbp[k], s3[k*16+tid], t);
            sbc[tid] = t;
        }
        __syncthreads();

        g_A[tid] = sA[tid];
        g_O[tid] = sO[tid];
        if (tid < 16) {
            float cs = 0.f, bb = sbc[tid];
            float cso = 0.f, bb2 = bo[tid];
            #pragma unroll
            for (int i = 0; i < 16; i++) {
                cs  += sA[i*16+tid];
                bb   = fmaf(sb[i], sAraw[i*16+tid], bb);
                cso += sO[i*16+tid];
                bb2  = fmaf(sb[i], Wo[i*16+tid], bb2);
            }
            g_csA[tid] = cs;  g_bA[tid] = bb;
            g_csO[tid] = cso; g_bO[tid] = bb2;
        }
        return;
    }

    // ------- attention block -------
    __shared__ float4 skv[256];     // KV quarter
    __shared__ float sw[102];       // Wq[32] Wk[32] Wv[32] bq bk bv

    if (tid < 32)        sw[tid] = Wq[tid];
    else if (tid < 64)   sw[tid] = Wk[tid - 32];
    else if (tid < 96)   sw[tid] = Wv[tid - 64];
    else if (tid < 98)   sw[tid] = bq[tid - 96];
    else if (tid < 100)  sw[tid] = bk[tid - 98];
    else if (tid < 102)  sw[tid] = bv[tid - 100];
    __syncthreads();

    int b     = blockIdx.z;
    int split = blockIdx.y;

    // Compute this thread's KV token (one per thread) into smem
    {
        int tkv = b * SS + split * 256 + tid;
        const float4* xp = reinterpret_cast<const float4*>(x + tkv * DD);
        float k0 = sw[98], k1 = sw[99], v0 = sw[100], v1 = sw[101];
        #pragma unroll
        for (int c4 = 0; c4 < 4; c4++) {
            float4 v = xp[c4];
            float xe[4] = {v.x, v.y, v.z, v.w};
            #pragma unroll
            for (int j = 0; j < 4; j++) {
                int i = c4 * 4 + j;
                k0 = fmaf(xe[j], sw[32+i*2+0], k0);
                k1 = fmaf(xe[j], sw[32+i*2+1], k1);
                v0 = fmaf(xe[j], sw[64+i*2+0], v0);
                v1 = fmaf(xe[j], sw[64+i*2+1], v1);
            }
        }
        skv[tid] = make_float4(k0, k1, v0, v1);
    }

    // Compute own Q (fold softmax scale + log2e)
    int s = blockIdx.x * 256 + tid;
    float q0, q1;
    {
        const float4* xp = reinterpret_cast<const float4*>(x + (b * SS + s) * DD);
        q0 = sw[96]; q1 = sw[97];
        #pragma unroll
        for (int c4 = 0; c4 < 4; c4++) {
            float4 v = xp[c4];
            float xe[4] = {v.x, v.y, v.z, v.w};
            #pragma unroll
            for (int j = 0; j < 4; j++) {
                int i = c4 * 4 + j;
                q0 = fmaf(xe[j], sw[i*2+0], q0);
                q1 = fmaf(xe[j], sw[i*2+1], q1);
            }
        }
        const float SC = 0.25f * 1.4426950408889634f;
        q0 *= SC; q1 *= SC;
    }
    __syncthreads();

    float l = 0.f, a0 = 0.f, a1 = 0.f;
    #pragma unroll 8
    for (int t = 0; t < 256; t++) {
        float4 kv = skv[t];
        float d = fmaf(q1, kv.y, q0 * kv.x);   // log2-domain score
        float p = ex2_approx(d);
        l  += p;
        a0 = fmaf(p, kv.z, a0);
        a1 = fmaf(p, kv.w, a1);
    }

    g_part[split * TOK + b * SS + s] = make_float4(l, a0, a1, 0.f);
}

// ---------------------------------------------------------------------------
// Kernel B: epilogue with LN-folded weights. 4 lanes per token.
// u = ctx@Wu + bu + x;  f = r*(u@A' - mu*csA) + bA;  out = r2*(f@O' - mu2*csO) + bO
// ---------------------------------------------------------------------------
__global__ void __launch_bounds__(256)
epilogue_kernel(const float* __restrict__ x,
                const float* __restrict__ Wu, const float* __restrict__ bu,
                float* __restrict__ out)
{
    __shared__ __align__(16) float sA[256], sO[256], sWu[32];
    __shared__ float sbu[16], scsA[16], sbA[16], scsO[16], sbO[16];

    int tid = threadIdx.x;
    int token = blockIdx.x * 64 + (tid >> 2);
    int q = tid & 3;

    sA[tid] = g_A[tid]; sO[tid] = g_O[tid];
    if (tid < 32) sWu[tid] = Wu[tid];
    if (tid < 16) {
        sbu[tid] = bu[tid];
        scsA[tid] = g_csA[tid]; sbA[tid] = g_bA[tid];
        scsO[tid] = g_csO[tid]; sbO[tid] = g_bO[tid];
    }
    __syncthreads();

    // Combine split partials: lane q loads split q, reduce over group of 4
    float4 p = g_part[q * TOK + token];
    float l = p.x, a0 = p.y, a1 = p.z;
    l  += __shfl_xor_sync(0xFFFFFFFFu, l, 1);
    a0 += __shfl_xor_sync(0xFFFFFFFFu, a0, 1);
    a1 += __shfl_xor_sync(0xFFFFFFFFu, a1, 1);
    l  += __shfl_xor_sync(0xFFFFFFFFu, l, 2);
    a0 += __shfl_xor_sync(0xFFFFFFFFu, a0, 2);
    a1 += __shfl_xor_sync(0xFFFFFFFFu, a1, 2);
    float inv = 1.0f / l;
    float c0 = a0 * inv, c1 = a1 * inv;

    // u quarter = ctx @ Wu + bu + x
    float4 xv = reinterpret_cast<const float4*>(x)[token * 4 + q];
    float u[4];
    u[0] = fmaf(c0, sWu[q*4+0], fmaf(c1, sWu[16+q*4+0], sbu[q*4+0])) + xv.x;
    u[1] = fmaf(c0, sWu[q*4+1], fmaf(c1, sWu[16+q*4+1], sbu[q*4+1])) + xv.y;
    u[2] = fmaf(c0, sWu[q*4+2], fmaf(c1, sWu[16+q*4+2], sbu[q*4+2])) + xv.z;
    u[3] = fmaf(c0, sWu[q*4+3], fmaf(c1, sWu[16+q*4+3], sbu[q*4+3])) + xv.w;

    // stats of u (one-pass)
    float su = (u[0] + u[1]) + (u[2] + u[3]);
    float s2 = fmaf(u[0],u[0], fmaf(u[1],u[1], fmaf(u[2],u[2], u[3]*u[3])));
    su += __shfl_xor_sync(0xFFFFFFFFu, su, 1);
    s2 += __shfl_xor_sync(0xFFFFFFFFu, s2, 1);
    su += __shfl_xor_sync(0xFFFFFFFFu, su, 2);
    s2 += __shfl_xor_sync(0xFFFFFFFFu, s2, 2);
    float mu = su * (1.0f / 16.0f);
    float r  = rsqrtf(fmaf(-mu, mu, s2 * (1.0f / 16.0f)) + 1e-5f);

    // w quarter = u @ A'   (raw u; LN folded into A', csA, bA)
    float w0 = 0.f, w1 = 0.f, w2 = 0.f, w3 = 0.f;
    #pragma unroll
    for (int i = 0; i < 16; i++) {
        float hv = __shfl_sync(0xFFFFFFFFu, u[i & 3], i >> 2, 4);
        float4 ww = *reinterpret_cast<const float4*>(sA + i * 16 + q * 4);
        w0 = fmaf(hv, ww.x, w0);
        w1 = fmaf(hv, ww.y, w1);
        w2 = fmaf(hv, ww.z, w2);
        w3 = fmaf(hv, ww.w, w3);
    }
    float f[4];
    f[0] = fmaf(r, fmaf(-mu, scsA[q*4+0], w0), sbA[q*4+0]);
    f[1] = fmaf(r, fmaf(-mu, scsA[q*4+1], w1), sbA[q*4+1]);
    f[2] = fmaf(r, fmaf(-mu, scsA[q*4+2], w2), sbA[q*4+2]);
    f[3] = fmaf(r, fmaf(-mu, scsA[q*4+3], w3), sbA[q*4+3]);

    // stats of f
    float sf = (f[0] + f[1]) + (f[2] + f[3]);
    float sf2 = fmaf(f[0],f[0], fmaf(f[1],f[1], fmaf(f[2],f[2], f[3]*f[3])));
    sf  += __shfl_xor_sync(0xFFFFFFFFu, sf, 1);
    sf2 += __shfl_xor_sync(0xFFFFFFFFu, sf2, 1);
    sf  += __shfl_xor_sync(0xFFFFFFFFu, sf, 2);
    sf2 += __shfl_xor_sync(0xFFFFFFFFu, sf2, 2);
    float mu2 = sf * (1.0f / 16.0f);
    float r2  = rsqrtf(fmaf(-mu2, mu2, sf2 * (1.0f / 16.0f)) + 1e-5f);

    // o quarter = f @ O'
    float o0 = 0.f, o1 = 0.f, o2 = 0.f, o3 = 0.f;
    #pragma unroll
    for (int i = 0; i < 16; i++) {
        float hv = __shfl_sync(0xFFFFFFFFu, f[i & 3], i >> 2, 4);
        float4 ww = *reinterpret_cast<const float4*>(sO + i * 16 + q * 4);
        o0 = fmaf(hv, ww.x, o0);
        o1 = fmaf(hv, ww.y, o1);
        o2 = fmaf(hv, ww.z, o2);
        o3 = fmaf(hv, ww.w, o3);
    }
    float4 res;
    res.x = fmaf(r2, fmaf(-mu2, scsO[q*4+0], o0), sbO[q*4+0]);
    res.y = fmaf(r2, fmaf(-mu2, scsO[q*4+1], o1), sbO[q*4+1]);
    res.z = fmaf(r2, fmaf(-mu2, scsO[q*4+2], o2), sbO[q*4+2]);
    res.w = fmaf(r2, fmaf(-mu2, scsO[q*4+3], o3), sbO[q*4+3]);

    reinterpret_cast<float4*>(out)[token * 4 + q] = res;
}

// ---------------------------------------------------------------------------
extern "C" void kernel_launch(void* const* d_in, const int* in_sizes, int n_in,
                              void* d_out, int out_size)
{
    const float* x    = (const float*)d_in[0];
    const float* Wq   = (const float*)d_in[1];
    const float* bq   = (const float*)d_in[2];
    const float* Wk   = (const float*)d_in[3];
    const float* bk   = (const float*)d_in[4];
    const float* Wv   = (const float*)d_in[5];
    const float* bv   = (const float*)d_in[6];
    const float* Wu   = (const float*)d_in[7];
    const float* bu   = (const float*)d_in[8];
    const float* ln_g = (const float*)d_in[9];
    const float* ln_b = (const float*)d_in[10];
    const float* W1   = (const float*)d_in[11];
    const float* b1   = (const float*)d_in[12];
    const float* W2   = (const float*)d_in[13];
    const float* b2   = (const float*)d_in[14];
    const float* W3   = (const float*)d_in[15];
    const float* b3   = (const float*)d_in[16];
    const float* Wo   = (const float*)d_in[17];
    const float* bo   = (const float*)d_in[18];
    float* out = (float*)d_out;

    dim3 agrid(5, NSPLIT, BB);
    attn_kernel<<<agrid, 256>>>(x, Wq, bq, Wk, bk, Wv, bv,
                                W1, b1, W2, b2, W3, b3, ln_g, ln_b, Wo, bo);

    epilogue_kernel<<<TOK / 64, 256>>>(x, Wu, bu, out);
}

// round 7
// speedup vs baseline: 1.0544x; 1.0544x over previous
#include <cuda_runtime.h>

#define BB 64
#define SS 1024
#define DD 16
#define NSPLIT 4
#define TOK (BB * SS)

// Scratch (allocation-free rule: __device__ globals)
__device__ float4 g_part[NSPLIT * TOK]; // per-split partial (l, a0, a1, 0)
__device__ float  g_A[256];             // diag(g) @ (W1W2W3 + I)
__device__ float  g_csA[16];            // column sums of g_A
__device__ float  g_bA[16];             // b @ (W1W2W3+I) + bc  (raw-A)
__device__ float  g_O[256];             // diag(g) @ Wo
__device__ float  g_csO[16];            // column sums of g_O
__device__ float  g_bO[16];             // b @ Wo + bo

__device__ __forceinline__ float ex2_approx(float x) {
    float y;
    asm("ex2.approx.f32 %0, %1;" : "=f"(y) : "f"(x));
    return y;
}

// ---------------------------------------------------------------------------
// Kernel A: fused QKV + attention (4-way KV block split) + weight precompute.
// Grid (5, NSPLIT, BB), 256 threads.
// ---------------------------------------------------------------------------
__global__ void __launch_bounds__(256)
attn_kernel(const float* __restrict__ x,
            const float* __restrict__ Wq, const float* __restrict__ bq,
            const float* __restrict__ Wk, const float* __restrict__ bk,
            const float* __restrict__ Wv, const float* __restrict__ bv,
            const float* __restrict__ W1, const float* __restrict__ b1,
            const float* __restrict__ W2, const float* __restrict__ b2,
            const float* __restrict__ W3, const float* __restrict__ b3,
            const float* __restrict__ ln_g, const float* __restrict__ ln_b,
            const float* __restrict__ Wo, const float* __restrict__ bo)
{
    int tid = threadIdx.x;

    if (blockIdx.x == 4) {
        // ------- precompute folded epilogue weights (one block) -------
        if (blockIdx.y != 0 || blockIdx.z != 0) return;
        __shared__ float s1[256], s2[256], s3[256], s12[256];
        __shared__ float sA[256], sAraw[256], sO[256];
        __shared__ float sbp[16], sbc[16], sg[16], sb[16];
        int r = tid >> 4, c = tid & 15;
        s1[tid] = W1[tid]; s2[tid] = W2[tid]; s3[tid] = W3[tid];
        if (tid < 16) { sg[tid] = ln_g[tid]; sb[tid] = ln_b[tid]; }
        __syncthreads();

        float acc = 0.f;
        #pragma unroll
        for (int k = 0; k < 16; k++) acc = fmaf(s1[r*16+k], s2[k*16+c], acc);
        s12[tid] = acc;
        if (tid < 16) {                 // b1@W2 + b2
            float t = b2[tid];
            #pragma unroll
            for (int k = 0; k < 16; k++) t = fmaf(b1[k], s2[k*16+tid], t);
            sbp[tid] = t;
        }
        __syncthreads();

        float w123 = 0.f;
        #pragma unroll
        for (int k = 0; k < 16; k++) w123 = fmaf(s12[r*16+k], s3[k*16+c], w123);
        float A = w123 + (r == c ? 1.0f : 0.0f);   // residual folded in
        sAraw[tid] = A;
        sA[tid] = sg[r] * A;
        sO[tid] = sg[r] * Wo[tid];
        if (tid < 16) {                 // bc = (b1@W2+b2)@W3 + b3
            float t = b3[tid];
            #pragma unroll
            for (int k = 0; k < 16; k++) t = fmaf(sbp[k], s3[k*16+tid], t);
            sbc[tid] = t;
        }
        __syncthreads();

        g_A[tid] = sA[tid];
        g_O[tid] = sO[tid];
        if (tid < 16) {
            float cs = 0.f, bb = sbc[tid];
            float cso = 0.f, bb2 = bo[tid];
            #pragma unroll
            for (int i = 0; i < 16; i++) {
                cs  += sA[i*16+tid];
                bb   = fmaf(sb[i], sAraw[i*16+tid], bb);
                cso += sO[i*16+tid];
                bb2  = fmaf(sb[i], Wo[i*16+tid], bb2);
            }
            g_csA[tid] = cs;  g_bA[tid] = bb;
            g_csO[tid] = cso; g_bO[tid] = bb2;
        }
        return;
    }

    // ------- attention block -------
    __shared__ float4 skv[256];     // KV quarter
    __shared__ float sw[102];       // Wq[32] Wk[32] Wv[32] bq bk bv

    if (tid < 32)        sw[tid] = Wq[tid];
    else if (tid < 64)   sw[tid] = Wk[tid - 32];
    else if (tid < 96)   sw[tid] = Wv[tid - 64];
    else if (tid < 98)   sw[tid] = bq[tid - 96];
    else if (tid < 100)  sw[tid] = bk[tid - 98];
    else if (tid < 102)  sw[tid] = bv[tid - 100];
    __syncthreads();

    int b     = blockIdx.z;
    int split = blockIdx.y;

    // Compute this thread's KV token (one per thread) into smem
    {
        int tkv = b * SS + split * 256 + tid;
        const float4* xp = reinterpret_cast<const float4*>(x + tkv * DD);
        float k0 = sw[98], k1 = sw[99], v0 = sw[100], v1 = sw[101];
        #pragma unroll
        for (int c4 = 0; c4 < 4; c4++) {
            float4 v = xp[c4];
            float xe[4] = {v.x, v.y, v.z, v.w};
            #pragma unroll
            for (int j = 0; j < 4; j++) {
                int i = c4 * 4 + j;
                k0 = fmaf(xe[j], sw[32+i*2+0], k0);
                k1 = fmaf(xe[j], sw[32+i*2+1], k1);
                v0 = fmaf(xe[j], sw[64+i*2+0], v0);
                v1 = fmaf(xe[j], sw[64+i*2+1], v1);
            }
        }
        skv[tid] = make_float4(k0, k1, v0, v1);
    }

    // Compute own Q (fold softmax scale + log2e)
    int s = blockIdx.x * 256 + tid;
    float q0, q1;
    {
        const float4* xp = reinterpret_cast<const float4*>(x + (b * SS + s) * DD);
        q0 = sw[96]; q1 = sw[97];
        #pragma unroll
        for (int c4 = 0; c4 < 4; c4++) {
            float4 v = xp[c4];
            float xe[4] = {v.x, v.y, v.z, v.w};
            #pragma unroll
            for (int j = 0; j < 4; j++) {
                int i = c4 * 4 + j;
                q0 = fmaf(xe[j], sw[i*2+0], q0);
                q1 = fmaf(xe[j], sw[i*2+1], q1);
            }
        }
        const float SC = 0.25f * 1.4426950408889634f;
        q0 *= SC; q1 *= SC;
    }
    __syncthreads();

    float l = 0.f, a0 = 0.f, a1 = 0.f;
    #pragma unroll 8
    for (int t = 0; t < 256; t++) {
        float4 kv = skv[t];
        float d = fmaf(q1, kv.y, q0 * kv.x);   // log2-domain score
        float p = ex2_approx(d);
        l  += p;
        a0 = fmaf(p, kv.z, a0);
        a1 = fmaf(p, kv.w, a1);
    }

    g_part[split * TOK + b * SS + s] = make_float4(l, a0, a1, 0.f);
}

// ---------------------------------------------------------------------------
// Kernel B: epilogue, 1 thread per token, LN-folded weights, no shfl.
// u = ctx@Wu+bu+x;  f = r*(u@A' - mu*csA) + bA;  out = r2*(f@O' - mu2*csO) + bO
// ---------------------------------------------------------------------------
__global__ void __launch_bounds__(256)
epilogue_kernel(const float* __restrict__ x,
                const float* __restrict__ Wu, const float* __restrict__ bu,
                float* __restrict__ out)
{
    __shared__ __align__(16) float sA[256], sO[256], sWu[32];
    __shared__ float sbu[16], scsA[16], sbA[16], scsO[16], sbO[16];

    int tid = threadIdx.x;
    int idx = blockIdx.x * 256 + tid;

    sA[tid] = g_A[tid & 255]; sO[tid] = g_O[tid & 255];
    if (tid < 32) sWu[tid] = Wu[tid];
    if (tid < 16) {
        sbu[tid] = bu[tid];
        scsA[tid] = g_csA[tid]; sbA[tid] = g_bA[tid];
        scsO[tid] = g_csO[tid]; sbO[tid] = g_bO[tid];
    }
    __syncthreads();

    // Combine the 4 KV-split partials
    float l = 0.f, a0 = 0.f, a1 = 0.f;
    #pragma unroll
    for (int sp = 0; sp < NSPLIT; sp++) {
        float4 p = g_part[sp * TOK + idx];
        l += p.x; a0 += p.y; a1 += p.z;
    }
    float inv = 1.0f / l;
    float c0 = a0 * inv, c1 = a1 * inv;

    // u = ctx @ Wu + bu + x
    float u[16];
    const float4* xp = reinterpret_cast<const float4*>(x + idx * DD);
    #pragma unroll
    for (int c4 = 0; c4 < 4; c4++) {
        float4 v = xp[c4];
        float xe[4] = {v.x, v.y, v.z, v.w};
        #pragma unroll
        for (int j = 0; j < 4; j++) {
            int i = c4 * 4 + j;
            u[i] = fmaf(c0, sWu[i], fmaf(c1, sWu[16 + i], sbu[i])) + xe[j];
        }
    }

    // stats of u
    float su = 0.f, s2 = 0.f;
    #pragma unroll
    for (int i = 0; i < 16; i++) { su += u[i]; s2 = fmaf(u[i], u[i], s2); }
    float mu = su * (1.0f / 16.0f);
    float r  = rsqrtf(fmaf(-mu, mu, s2 * (1.0f / 16.0f)) + 1e-5f);

    // w = u @ A'  then f = r*(w - mu*csA) + bA
    float f[16];
    {
        float acc[16];
        #pragma unroll
        for (int j = 0; j < 16; j++) acc[j] = 0.f;
        #pragma unroll
        for (int i = 0; i < 16; i++) {
            float hv = u[i];
            const float4* wr = reinterpret_cast<const float4*>(sA + i * 16);
            #pragma unroll
            for (int j4 = 0; j4 < 4; j4++) {
                float4 w = wr[j4];
                acc[4*j4+0] = fmaf(hv, w.x, acc[4*j4+0]);
                acc[4*j4+1] = fmaf(hv, w.y, acc[4*j4+1]);
                acc[4*j4+2] = fmaf(hv, w.z, acc[4*j4+2]);
                acc[4*j4+3] = fmaf(hv, w.w, acc[4*j4+3]);
            }
        }
        #pragma unroll
        for (int j = 0; j < 16; j++)
            f[j] = fmaf(r, fmaf(-mu, scsA[j], acc[j]), sbA[j]);
    }

    // stats of f
    float sf = 0.f, sf2 = 0.f;
    #pragma unroll
    for (int i = 0; i < 16; i++) { sf += f[i]; sf2 = fmaf(f[i], f[i], sf2); }
    float mu2 = sf * (1.0f / 16.0f);
    float r2  = rsqrtf(fmaf(-mu2, mu2, sf2 * (1.0f / 16.0f)) + 1e-5f);

    // o = f @ O'  then out = r2*(o - mu2*csO) + bO
    float o[16];
    {
        float acc[16];
        #pragma unroll
        for (int j = 0; j < 16; j++) acc[j] = 0.f;
        #pragma unroll
        for (int i = 0; i < 16; i++) {
            float hv = f[i];
            const float4* wr = reinterpret_cast<const float4*>(sO + i * 16);
            #pragma unroll
            for (int j4 = 0; j4 < 4; j4++) {
                float4 w = wr[j4];
                acc[4*j4+0] = fmaf(hv, w.x, acc[4*j4+0]);
                acc[4*j4+1] = fmaf(hv, w.y, acc[4*j4+1]);
                acc[4*j4+2] = fmaf(hv, w.z, acc[4*j4+2]);
                acc[4*j4+3] = fmaf(hv, w.w, acc[4*j4+3]);
            }
        }
        #pragma unroll
        for (int j = 0; j < 16; j++)
            o[j] = fmaf(r2, fmaf(-mu2, scsO[j], acc[j]), sbO[j]);
    }

    float4* op = reinterpret_cast<float4*>(out + idx * DD);
    #pragma unroll
    for (int c4 = 0; c4 < 4; c4++)
        op[c4] = make_float4(o[4*c4+0], o[4*c4+1], o[4*c4+2], o[4*c4+3]);
}

// ---------------------------------------------------------------------------
extern "C" void kernel_launch(void* const* d_in, const int* in_sizes, int n_in,
                              void* d_out, int out_size)
{
    const float* x    = (const float*)d_in[0];
    const float* Wq   = (const float*)d_in[1];
    const float* bq   = (const float*)d_in[2];
    const float* Wk   = (const float*)d_in[3];
    const float* bk   = (const float*)d_in[4];
    const float* Wv   = (const float*)d_in[5];
    const float* bv   = (const float*)d_in[6];
    const float* Wu   = (const float*)d_in[7];
    const float* bu   = (const float*)d_in[8];
    const float* ln_g = (const float*)d_in[9];
    const float* ln_b = (const float*)d_in[10];
    const float* W1   = (const float*)d_in[11];
    const float* b1   = (const float*)d_in[12];
    const float* W2   = (const float*)d_in[13];
    const float* b2   = (const float*)d_in[14];
    const float* W3   = (const float*)d_in[15];
    const float* b3   = (const float*)d_in[16];
    const float* Wo   = (const float*)d_in[17];
    const float* bo   = (const float*)d_in[18];
    float* out = (float*)d_out;

    dim3 agrid(5, NSPLIT, BB);
    attn_kernel<<<agrid, 256>>>(x, Wq, bq, Wk, bk, Wv, bv,
                                W1, b1, W2, b2, W3, b3, ln_g, ln_b, Wo, bo);

    epilogue_kernel<<<TOK / 256, 256>>>(x, Wu, bu, out);
}